// round 10
// baseline (speedup 1.0000x reference)
#include <cuda_runtime.h>
#include <math.h>
#include <stdint.h>

#define N_NODES 25000
#define N_EDGES 400000
#define EMBED   128
#define NHEADS  8
#define DKH     16

// ---------------- scratch (static device globals; no allocation) -----------
__device__ __align__(16) float g_Q[N_NODES * EMBED];
__device__ __align__(16) float g_K[N_NODES * EMBED];
__device__ __align__(16) float g_V[N_NODES * EMBED];
__device__ __align__(16) float g_agg[N_NODES * EMBED];   // UNNORMALIZED sum(e*v)
__device__ float g_z[N_NODES * NHEADS];                  // sum of exp
__device__ int   g_cnt[N_NODES];                         // edges per dst
__device__ int   g_start[N_NODES];                       // exclusive prefix
__device__ int   g_cur[N_NODES];                         // scatter cursor
__device__ __align__(8) int2 g_sedge[N_EDGES];           // (eid, src) sorted by dst

__device__ __forceinline__ void red_add_v4(float* p, float a, float b, float c, float d) {
    asm volatile("red.global.add.v4.f32 [%0], {%1, %2, %3, %4};"
                 :: "l"(p), "f"(a), "f"(b), "f"(c), "f"(d) : "memory");
}

// ---------------- K0: init (agg, z, counters) ------------------------------
__global__ void init_kernel() {
    int i = blockIdx.x * blockDim.x + threadIdx.x;
    if (i < N_NODES * EMBED) g_agg[i] = 0.0f;
    if (i < N_NODES * NHEADS) g_z[i] = 0.0f;
    if (i < N_NODES) g_cnt[i] = 0;
}

// ---------------- sort by dst: hist -> scan -> scatter ---------------------
__global__ void hist_kernel(const int* __restrict__ ei) {
    int e = blockIdx.x * blockDim.x + threadIdx.x;
    if (e < N_EDGES) atomicAdd(&g_cnt[ei[e]], 1);
}

__global__ void scan_kernel() {   // single block, 1024 threads
    __shared__ int s[1024];
    int t = threadIdx.x;
    const int CH = (N_NODES + 1023) / 1024;   // 25
    int b0 = t * CH;
    int sum = 0;
    for (int i = 0; i < CH; ++i) {
        int idx = b0 + i;
        if (idx < N_NODES) sum += g_cnt[idx];
    }
    s[t] = sum;
    __syncthreads();
    for (int off = 1; off < 1024; off <<= 1) {
        int v = (t >= off) ? s[t - off] : 0;
        __syncthreads();
        s[t] += v;
        __syncthreads();
    }
    int excl = (t == 0) ? 0 : s[t - 1];
    for (int i = 0; i < CH; ++i) {
        int idx = b0 + i;
        if (idx < N_NODES) {
            g_start[idx] = excl;
            g_cur[idx]   = excl;
            excl += g_cnt[idx];
        }
    }
}

__global__ void scatter_kernel(const int* __restrict__ ei) {
    int e = blockIdx.x * blockDim.x + threadIdx.x;
    if (e < N_EDGES) {
        int dst = ei[e];
        int src = ei[N_EDGES + e];
        int pos = atomicAdd(&g_cur[dst], 1);
        g_sedge[pos] = make_int2(e, src);
    }
}

// ================= tf32 tensor-core GEMM: Out = X @ W^T + b ================
#define GM_BLK 128
#define GKC    32

__device__ __forceinline__ float to_tf32(float x) {
    float r;
    asm("cvt.rna.tf32.f32 %0, %1;" : "=f"(r) : "f"(x));
    return r;
}

__device__ __forceinline__ void mma_tf32(float c[4], const unsigned a[4], const unsigned b[2]) {
    asm volatile(
        "mma.sync.aligned.m16n8k8.row.col.f32.tf32.tf32.f32 "
        "{%0,%1,%2,%3}, {%4,%5,%6,%7}, {%8,%9}, {%0,%1,%2,%3};\n"
        : "+f"(c[0]), "+f"(c[1]), "+f"(c[2]), "+f"(c[3])
        : "r"(a[0]), "r"(a[1]), "r"(a[2]), "r"(a[3]), "r"(b[0]), "r"(b[1]));
}

// norm_z: if nonzero, divide X rows by per-head z during staging (out proj)
__device__ __forceinline__
void gemm_body(const float* __restrict__ X, const float* __restrict__ W,
               const float* __restrict__ bias, float* __restrict__ Out,
               int nrows, float* xs, float* ws, int n0, int norm_z) {
    int tid  = threadIdx.x;
    int lane = tid & 31;
    int w    = tid >> 5;

    int mq = w & 3;    // rows 32*mq .. +31
    int nh = w >> 2;   // cols 64*nh .. +63

    float c[2][8][4];
#pragma unroll
    for (int mi = 0; mi < 2; ++mi)
#pragma unroll
        for (int ni = 0; ni < 8; ++ni)
#pragma unroll
            for (int q = 0; q < 4; ++q) c[mi][ni][q] = 0.0f;

    for (int kc = 0; kc < EMBED; kc += GKC) {
#pragma unroll
        for (int r = 0; r < 4; ++r) {
            int idx = r * 256 + tid;
            int n  = idx >> 3;
            int k4 = idx & 7;
            float4 v = make_float4(0.f, 0.f, 0.f, 0.f);
            if (n0 + n < nrows) {
                v = *(const float4*)(X + (size_t)(n0 + n) * EMBED + kc + 4 * k4);
                if (norm_z) {
                    int d4 = (kc >> 2) + k4;             // float4 index in row
                    float z = g_z[(n0 + n) * NHEADS + (d4 >> 2)];
                    float inv = (z > 0.0f) ? (1.0f / z) : 0.0f;
                    v.x *= inv; v.y *= inv; v.z *= inv; v.w *= inv;
                }
            }
            v.x = to_tf32(v.x); v.y = to_tf32(v.y);
            v.z = to_tf32(v.z); v.w = to_tf32(v.w);
            int ks = (4 * k4) ^ ((n & 7) << 2);
            *(float4*)(xs + n * GKC + ks) = v;
        }
#pragma unroll
        for (int r = 0; r < 4; ++r) {
            int idx = r * 256 + tid;
            int j  = idx >> 3;
            int k4 = idx & 7;
            float4 v = *(const float4*)(W + (size_t)j * EMBED + kc + 4 * k4);
            v.x = to_tf32(v.x); v.y = to_tf32(v.y);
            v.z = to_tf32(v.z); v.w = to_tf32(v.w);
            int ks = (4 * k4) ^ ((j & 7) << 2);
            *(float4*)(ws + j * GKC + ks) = v;
        }
        __syncthreads();

#pragma unroll
        for (int k0 = 0; k0 < GKC; k0 += 8) {
            unsigned a[2][4];
#pragma unroll
            for (int mi = 0; mi < 2; ++mi) {
                int rrow = mq * 32 + mi * 16 + (lane >> 2);
                int sw = (rrow & 7) << 2;
                int kA = k0 + (lane & 3);
                a[mi][0] = __float_as_uint(xs[rrow * GKC + (kA ^ sw)]);
                a[mi][1] = __float_as_uint(xs[(rrow + 8) * GKC + (kA ^ sw)]);
                a[mi][2] = __float_as_uint(xs[rrow * GKC + ((kA + 4) ^ sw)]);
                a[mi][3] = __float_as_uint(xs[(rrow + 8) * GKC + ((kA + 4) ^ sw)]);
            }
            unsigned b[8][2];
#pragma unroll
            for (int ni = 0; ni < 8; ++ni) {
                int j = nh * 64 + ni * 8 + (lane >> 2);
                int sw = (j & 7) << 2;
                int kB = k0 + (lane & 3);
                b[ni][0] = __float_as_uint(ws[j * GKC + (kB ^ sw)]);
                b[ni][1] = __float_as_uint(ws[j * GKC + ((kB + 4) ^ sw)]);
            }
#pragma unroll
            for (int mi = 0; mi < 2; ++mi)
#pragma unroll
                for (int ni = 0; ni < 8; ++ni)
                    mma_tf32(c[mi][ni], a[mi], b[ni]);
        }
        __syncthreads();
    }

#pragma unroll
    for (int mi = 0; mi < 2; ++mi) {
        int r = n0 + mq * 32 + mi * 16 + (lane >> 2);
#pragma unroll
        for (int ni = 0; ni < 8; ++ni) {
            int col = nh * 64 + ni * 8 + 2 * (lane & 3);
            float b0 = bias[col], b1 = bias[col + 1];
            if (r < nrows)
                *(float2*)(Out + (size_t)r * EMBED + col) =
                    make_float2(c[mi][ni][0] + b0, c[mi][ni][1] + b1);
            if (r + 8 < nrows)
                *(float2*)(Out + (size_t)(r + 8) * EMBED + col) =
                    make_float2(c[mi][ni][2] + b0, c[mi][ni][3] + b1);
        }
    }
}

// fused Q/K/V: blockIdx.y selects projection
__global__ __launch_bounds__(256)
void qkv3_kernel(const float* __restrict__ X,
                 const float* __restrict__ Wq, const float* __restrict__ bq,
                 const float* __restrict__ Wk, const float* __restrict__ bk,
                 const float* __restrict__ Wv, const float* __restrict__ bv) {
    __shared__ float xs[GM_BLK * GKC];
    __shared__ float ws[EMBED * GKC];
    const float* W; const float* b; float* O;
    if (blockIdx.y == 0)      { W = Wq; b = bq; O = g_Q; }
    else if (blockIdx.y == 1) { W = Wk; b = bk; O = g_K; }
    else                      { W = Wv; b = bv; O = g_V; }
    gemm_body(X, W, b, O, N_NODES, xs, ws, blockIdx.x * GM_BLK, 0);
}

__global__ __launch_bounds__(256)
void out_gemm_kernel(const float* __restrict__ X,
                     const float* __restrict__ W,
                     const float* __restrict__ bias,
                     float* __restrict__ Out,
                     int nrows) {
    __shared__ float xs[GM_BLK * GKC];
    __shared__ float ws[EMBED * GKC];
    gemm_body(X, W, bias, Out, nrows, xs, ws, blockIdx.x * GM_BLK, 1);
}

// ---------------- gather: coalesced rows, 2 warps per node -----------------
// Warp pair per dst node, each processing alternating 4-edge groups (stride 8).
// Lane l owns floats [l*4, l*4+4) of each row (head hl = l>>2); K/V rows are
// fetched by ONE coalesced LDG.128 per edge. Quad shfl reduces dots per head.
// Partial results combined across the warp pair via red.add into g_agg / g_z.
// Softmax shift-invariance: logits are O(8), no max-subtraction needed.
__global__ __launch_bounds__(256)
void gather_kernel(const float* __restrict__ bias,
                   float* __restrict__ out_logits) {
    int gw = (blockIdx.x * blockDim.x + threadIdx.x) >> 5;
    if (gw >= 2 * N_NODES) return;
    int n    = gw >> 1;
    int half = gw & 1;
    int lane = threadIdx.x & 31;
    int hl   = lane >> 2;          // head owned by this lane's quad

    float4 q = *(const float4*)(g_Q + n * EMBED + lane * 4);
    float4 acc = make_float4(0.f, 0.f, 0.f, 0.f);
    float accz = 0.0f;

    int cnt  = g_cnt[n];
    int base = g_start[n];

    for (int i = half * 4; i < cnt; i += 8) {
        int m = cnt - i;   // edges valid this group (>=1)

        // lanes 0..3 fetch (eid, src); broadcast to warp
        int2 se = make_int2(0, 0);
        if (lane < 4 && lane < m) se = g_sedge[base + i + lane];
        int eid[4], src[4];
#pragma unroll
        for (int j = 0; j < 4; ++j) {
            eid[j] = __shfl_sync(0xffffffffu, se.x, j);
            src[j] = __shfl_sync(0xffffffffu, se.y, j);
        }

        float4 k0 = *(const float4*)(g_K + (size_t)src[0] * EMBED + lane * 4);
        float4 k1 = *(const float4*)(g_K + (size_t)src[1] * EMBED + lane * 4);
        float4 k2 = *(const float4*)(g_K + (size_t)src[2] * EMBED + lane * 4);
        float4 k3 = *(const float4*)(g_K + (size_t)src[3] * EMBED + lane * 4);
        float4 v0 = *(const float4*)(g_V + (size_t)src[0] * EMBED + lane * 4);
        float4 v1 = *(const float4*)(g_V + (size_t)src[1] * EMBED + lane * 4);
        float4 v2 = *(const float4*)(g_V + (size_t)src[2] * EMBED + lane * 4);
        float4 v3 = *(const float4*)(g_V + (size_t)src[3] * EMBED + lane * 4);
        float b0 = bias[eid[0] * NHEADS + hl];
        float b1 = bias[eid[1] * NHEADS + hl];
        float b2 = bias[eid[2] * NHEADS + hl];
        float b3 = bias[eid[3] * NHEADS + hl];

        float d0 = q.x*k0.x + q.y*k0.y + q.z*k0.z + q.w*k0.w;
        float d1 = q.x*k1.x + q.y*k1.y + q.z*k1.z + q.w*k1.w;
        float d2 = q.x*k2.x + q.y*k2.y + q.z*k2.z + q.w*k2.w;
        float d3 = q.x*k3.x + q.y*k3.y + q.z*k3.z + q.w*k3.w;
        d0 += __shfl_xor_sync(0xffffffffu, d0, 1);
        d0 += __shfl_xor_sync(0xffffffffu, d0, 2);
        d1 += __shfl_xor_sync(0xffffffffu, d1, 1);
        d1 += __shfl_xor_sync(0xffffffffu, d1, 2);
        d2 += __shfl_xor_sync(0xffffffffu, d2, 1);
        d2 += __shfl_xor_sync(0xffffffffu, d2, 2);
        d3 += __shfl_xor_sync(0xffffffffu, d3, 1);
        d3 += __shfl_xor_sync(0xffffffffu, d3, 2);

        float l0 = 0.25f * d0 + b0;   // scale = 1/sqrt(16)
        float l1 = 0.25f * d1 + b1;
        float l2 = 0.25f * d2 + b2;
        float l3 = 0.25f * d3 + b3;

        bool w0 = (lane & 3) == 0;
        if (w0)          out_logits[eid[0] * NHEADS + hl] = l0;
        if (w0 && m > 1) out_logits[eid[1] * NHEADS + hl] = l1;
        if (w0 && m > 2) out_logits[eid[2] * NHEADS + hl] = l2;
        if (w0 && m > 3) out_logits[eid[3] * NHEADS + hl] = l3;

        float e0 = __expf(l0);
        float e1 = (m > 1) ? __expf(l1) : 0.0f;
        float e2 = (m > 2) ? __expf(l2) : 0.0f;
        float e3 = (m > 3) ? __expf(l3) : 0.0f;
        accz += e0 + e1 + e2 + e3;

        acc.x += e0*v0.x + e1*v1.x + e2*v2.x + e3*v3.x;
        acc.y += e0*v0.y + e1*v1.y + e2*v2.y + e3*v3.y;
        acc.z += e0*v0.z + e1*v1.z + e2*v2.z + e3*v3.z;
        acc.w += e0*v0.w + e1*v1.w + e2*v2.w + e3*v3.w;
    }

    // combine across the warp pair in memory
    if ((lane & 3) == 0 && accz != 0.0f)
        atomicAdd(&g_z[n * NHEADS + hl], accz);
    red_add_v4(g_agg + n * EMBED + lane * 4, acc.x, acc.y, acc.z, acc.w);
}

// ---------------- launch --------------------------------------------------
extern "C" void kernel_launch(void* const* d_in, const int* in_sizes, int n_in,
                              void* d_out, int out_size) {
    const float* x    = (const float*)d_in[0];
    const int*   ei   = (const int*)d_in[1];
    const float* bias = (const float*)d_in[2];
    const float* Wq   = (const float*)d_in[3];
    const float* bq   = (const float*)d_in[4];
    const float* Wk   = (const float*)d_in[5];
    const float* bk   = (const float*)d_in[6];
    const float* Wv   = (const float*)d_in[7];
    const float* bv   = (const float*)d_in[8];
    const float* Wo   = (const float*)d_in[9];
    const float* bo   = (const float*)d_in[10];

    float* out        = (float*)d_out;                       // [N_NODES, 128]
    float* out_logits = (float*)d_out + N_NODES * EMBED;     // [E, H, 1]

    int initN = N_NODES * EMBED;
    init_kernel<<<(initN + 255) / 256, 256>>>();
    hist_kernel<<<(N_EDGES + 255) / 256, 256>>>(ei);
    scan_kernel<<<1, 1024>>>();
    scatter_kernel<<<(N_EDGES + 255) / 256, 256>>>(ei);

    float* gA; cudaGetSymbolAddress((void**)&gA, g_agg);

    int gblk = (N_NODES + GM_BLK - 1) / GM_BLK;
    dim3 qkvgrid(gblk, 3);
    qkv3_kernel<<<qkvgrid, 256>>>(x, Wq, bq, Wk, bk, Wv, bv);

    int nwarp_blocks = (2 * N_NODES * 32 + 255) / 256;
    gather_kernel<<<nwarp_blocks, 256>>>(bias, out_logits);

    out_gemm_kernel<<<gblk, 256>>>(gA, Wo, bo, out, N_NODES);
}

// round 12
// speedup vs baseline: 1.1604x; 1.1604x over previous
#include <cuda_runtime.h>
#include <cuda_fp16.h>
#include <math.h>
#include <stdint.h>

#define N_NODES 25000
#define N_EDGES 400000
#define EMBED   128
#define NHEADS  8
#define DKH     16

// ---------------- scratch (static device globals; no allocation) -----------
__device__ __align__(16) __half g_Qh[N_NODES * EMBED];   // fp16 Q (gather-only)
__device__ __align__(16) __half g_Kh[N_NODES * EMBED];   // fp16 K (gather-only)
__device__ __align__(16) __half g_Vh[N_NODES * EMBED];   // fp16 V (gather-only)
__device__ __align__(16) float g_agg[N_NODES * EMBED];   // normalized sum(e*v)/z
__device__ int   g_cnt[N_NODES];                         // edges per dst
__device__ int   g_start[N_NODES];                       // exclusive prefix
__device__ int   g_cur[N_NODES];                         // scatter cursor
__device__ __align__(8) int2 g_sedge[N_EDGES];           // (eid, src) sorted by dst

// ---------------- K0: init (counters only) --------------------------------
__global__ void init_kernel() {
    int i = blockIdx.x * blockDim.x + threadIdx.x;
    if (i < N_NODES) g_cnt[i] = 0;
}

// ---------------- sort by dst: hist -> scan -> scatter ---------------------
__global__ void hist_kernel(const int* __restrict__ ei) {
    int e = blockIdx.x * blockDim.x + threadIdx.x;
    if (e < N_EDGES) atomicAdd(&g_cnt[ei[e]], 1);
}

__global__ void scan_kernel() {   // single block, 1024 threads
    __shared__ int s[1024];
    int t = threadIdx.x;
    const int CH = (N_NODES + 1023) / 1024;   // 25
    int b0 = t * CH;
    int sum = 0;
    for (int i = 0; i < CH; ++i) {
        int idx = b0 + i;
        if (idx < N_NODES) sum += g_cnt[idx];
    }
    s[t] = sum;
    __syncthreads();
    for (int off = 1; off < 1024; off <<= 1) {
        int v = (t >= off) ? s[t - off] : 0;
        __syncthreads();
        s[t] += v;
        __syncthreads();
    }
    int excl = (t == 0) ? 0 : s[t - 1];
    for (int i = 0; i < CH; ++i) {
        int idx = b0 + i;
        if (idx < N_NODES) {
            g_start[idx] = excl;
            g_cur[idx]   = excl;
            excl += g_cnt[idx];
        }
    }
}

__global__ void scatter_kernel(const int* __restrict__ ei) {
    int e = blockIdx.x * blockDim.x + threadIdx.x;
    if (e < N_EDGES) {
        int dst = ei[e];
        int src = ei[N_EDGES + e];
        int pos = atomicAdd(&g_cur[dst], 1);
        g_sedge[pos] = make_int2(e, src);
    }
}

// ================= tf32 tensor-core GEMM: Out = X @ W^T + b ================
#define GM_BLK 128
#define GKC    32

__device__ __forceinline__ float to_tf32(float x) {
    float r;
    asm("cvt.rna.tf32.f32 %0, %1;" : "=f"(r) : "f"(x));
    return r;
}

__device__ __forceinline__ void mma_tf32(float c[4], const unsigned a[4], const unsigned b[2]) {
    asm volatile(
        "mma.sync.aligned.m16n8k8.row.col.f32.tf32.tf32.f32 "
        "{%0,%1,%2,%3}, {%4,%5,%6,%7}, {%8,%9}, {%0,%1,%2,%3};\n"
        : "+f"(c[0]), "+f"(c[1]), "+f"(c[2]), "+f"(c[3])
        : "r"(a[0]), "r"(a[1]), "r"(a[2]), "r"(a[3]), "r"(b[0]), "r"(b[1]));
}

// out_half: if nonzero, Out is a __half* buffer (fp16 store for gather inputs)
__device__ __forceinline__
void gemm_body(const float* __restrict__ X, const float* __restrict__ W,
               const float* __restrict__ bias, void* __restrict__ Out,
               int nrows, float* xs, float* ws, int n0, int out_half) {
    int tid  = threadIdx.x;
    int lane = tid & 31;
    int w    = tid >> 5;

    int mq = w & 3;    // rows 32*mq .. +31
    int nh = w >> 2;   // cols 64*nh .. +63

    float c[2][8][4];
#pragma unroll
    for (int mi = 0; mi < 2; ++mi)
#pragma unroll
        for (int ni = 0; ni < 8; ++ni)
#pragma unroll
            for (int q = 0; q < 4; ++q) c[mi][ni][q] = 0.0f;

    for (int kc = 0; kc < EMBED; kc += GKC) {
#pragma unroll
        for (int r = 0; r < 4; ++r) {
            int idx = r * 256 + tid;
            int n  = idx >> 3;
            int k4 = idx & 7;
            float4 v = make_float4(0.f, 0.f, 0.f, 0.f);
            if (n0 + n < nrows)
                v = *(const float4*)(X + (size_t)(n0 + n) * EMBED + kc + 4 * k4);
            v.x = to_tf32(v.x); v.y = to_tf32(v.y);
            v.z = to_tf32(v.z); v.w = to_tf32(v.w);
            int ks = (4 * k4) ^ ((n & 7) << 2);
            *(float4*)(xs + n * GKC + ks) = v;
        }
#pragma unroll
        for (int r = 0; r < 4; ++r) {
            int idx = r * 256 + tid;
            int j  = idx >> 3;
            int k4 = idx & 7;
            float4 v = *(const float4*)(W + (size_t)j * EMBED + kc + 4 * k4);
            v.x = to_tf32(v.x); v.y = to_tf32(v.y);
            v.z = to_tf32(v.z); v.w = to_tf32(v.w);
            int ks = (4 * k4) ^ ((j & 7) << 2);
            *(float4*)(ws + j * GKC + ks) = v;
        }
        __syncthreads();

#pragma unroll
        for (int k0 = 0; k0 < GKC; k0 += 8) {
            unsigned a[2][4];
#pragma unroll
            for (int mi = 0; mi < 2; ++mi) {
                int rrow = mq * 32 + mi * 16 + (lane >> 2);
                int sw = (rrow & 7) << 2;
                int kA = k0 + (lane & 3);
                a[mi][0] = __float_as_uint(xs[rrow * GKC + (kA ^ sw)]);
                a[mi][1] = __float_as_uint(xs[(rrow + 8) * GKC + (kA ^ sw)]);
                a[mi][2] = __float_as_uint(xs[rrow * GKC + ((kA + 4) ^ sw)]);
                a[mi][3] = __float_as_uint(xs[(rrow + 8) * GKC + ((kA + 4) ^ sw)]);
            }
            unsigned b[8][2];
#pragma unroll
            for (int ni = 0; ni < 8; ++ni) {
                int j = nh * 64 + ni * 8 + (lane >> 2);
                int sw = (j & 7) << 2;
                int kB = k0 + (lane & 3);
                b[ni][0] = __float_as_uint(ws[j * GKC + (kB ^ sw)]);
                b[ni][1] = __float_as_uint(ws[j * GKC + ((kB + 4) ^ sw)]);
            }
#pragma unroll
            for (int mi = 0; mi < 2; ++mi)
#pragma unroll
                for (int ni = 0; ni < 8; ++ni)
                    mma_tf32(c[mi][ni], a[mi], b[ni]);
        }
        __syncthreads();
    }

#pragma unroll
    for (int mi = 0; mi < 2; ++mi) {
        int r = n0 + mq * 32 + mi * 16 + (lane >> 2);
#pragma unroll
        for (int ni = 0; ni < 8; ++ni) {
            int col = nh * 64 + ni * 8 + 2 * (lane & 3);
            float b0 = bias[col], b1 = bias[col + 1];
            if (out_half) {
                __half* Oh = (__half*)Out;
                if (r < nrows)
                    *(__half2*)(Oh + (size_t)r * EMBED + col) =
                        __floats2half2_rn(c[mi][ni][0] + b0, c[mi][ni][1] + b1);
                if (r + 8 < nrows)
                    *(__half2*)(Oh + (size_t)(r + 8) * EMBED + col) =
                        __floats2half2_rn(c[mi][ni][2] + b0, c[mi][ni][3] + b1);
            } else {
                float* Of = (float*)Out;
                if (r < nrows)
                    *(float2*)(Of + (size_t)r * EMBED + col) =
                        make_float2(c[mi][ni][0] + b0, c[mi][ni][1] + b1);
                if (r + 8 < nrows)
                    *(float2*)(Of + (size_t)(r + 8) * EMBED + col) =
                        make_float2(c[mi][ni][2] + b0, c[mi][ni][3] + b1);
            }
        }
    }
}

// fused Q/K/V (fp16 out): blockIdx.y selects projection
__global__ __launch_bounds__(256)
void qkv3_kernel(const float* __restrict__ X,
                 const float* __restrict__ Wq, const float* __restrict__ bq,
                 const float* __restrict__ Wk, const float* __restrict__ bk,
                 const float* __restrict__ Wv, const float* __restrict__ bv) {
    __shared__ float xs[GM_BLK * GKC];
    __shared__ float ws[EMBED * GKC];
    const float* W; const float* b; __half* O;
    if (blockIdx.y == 0)      { W = Wq; b = bq; O = g_Qh; }
    else if (blockIdx.y == 1) { W = Wk; b = bk; O = g_Kh; }
    else                      { W = Wv; b = bv; O = g_Vh; }
    gemm_body(X, W, b, O, N_NODES, xs, ws, blockIdx.x * GM_BLK, 1);
}

__global__ __launch_bounds__(256)
void gemm_tf32_kernel(const float* __restrict__ X,
                      const float* __restrict__ W,
                      const float* __restrict__ bias,
                      float* __restrict__ Out,
                      int nrows) {
    __shared__ float xs[GM_BLK * GKC];
    __shared__ float ws[EMBED * GKC];
    gemm_body(X, W, bias, Out, nrows, xs, ws, blockIdx.x * GM_BLK, 0);
}

// ---------------- gather: coalesced fp16 rows, one warp per node -----------
// One warp per dst node, 4 edges per iteration. Lane l owns values
// [l*4, l*4+4) of each 128-half row = 8 bytes -> each K/V row is ONE
// warp-coalesced LDG.64 (256B = 2 lines = 2 wavefronts). Quad shfl reduces
// dots per head (head hl = l>>2). Accumulation fp32; softmax shift-invariant
// (logits O(8), no max-subtraction). Stores NORMALIZED fp32 agg.
__device__ __forceinline__ float4 h4_to_f4(uint2 u) {
    float2 fa = __half22float2(*reinterpret_cast<__half2*>(&u.x));
    float2 fb = __half22float2(*reinterpret_cast<__half2*>(&u.y));
    return make_float4(fa.x, fa.y, fb.x, fb.y);
}

__global__ __launch_bounds__(256)
void gather_kernel(const float* __restrict__ bias,
                   float* __restrict__ out_logits) {
    int warp = (blockIdx.x * blockDim.x + threadIdx.x) >> 5;
    if (warp >= N_NODES) return;
    int lane = threadIdx.x & 31;
    int hl   = lane >> 2;          // head owned by this lane's quad
    int n = warp;

    float4 q = h4_to_f4(*((const uint2*)(g_Qh + (size_t)n * EMBED) + lane));
    float4 acc = make_float4(0.f, 0.f, 0.f, 0.f);
    float accz = 0.0f;

    int cnt  = g_cnt[n];
    int base = g_start[n];

    for (int i = 0; i < cnt; i += 4) {
        int m = cnt - i;   // edges valid this iter (>=1)

        // lanes 0..3 fetch (eid, src); broadcast to warp
        int2 se = make_int2(0, 0);
        if (lane < 4 && lane < m) se = g_sedge[base + i + lane];
        int eid[4], src[4];
#pragma unroll
        for (int j = 0; j < 4; ++j) {
            eid[j] = __shfl_sync(0xffffffffu, se.x, j);
            src[j] = __shfl_sync(0xffffffffu, se.y, j);
        }

        // coalesced fp16 K rows: one LDG.64 per edge, whole warp
        float4 k0 = h4_to_f4(*((const uint2*)(g_Kh + (size_t)src[0] * EMBED) + lane));
        float4 k1 = h4_to_f4(*((const uint2*)(g_Kh + (size_t)src[1] * EMBED) + lane));
        float4 k2 = h4_to_f4(*((const uint2*)(g_Kh + (size_t)src[2] * EMBED) + lane));
        float4 k3 = h4_to_f4(*((const uint2*)(g_Kh + (size_t)src[3] * EMBED) + lane));
        // coalesced fp16 V rows
        float4 v0 = h4_to_f4(*((const uint2*)(g_Vh + (size_t)src[0] * EMBED) + lane));
        float4 v1 = h4_to_f4(*((const uint2*)(g_Vh + (size_t)src[1] * EMBED) + lane));
        float4 v2 = h4_to_f4(*((const uint2*)(g_Vh + (size_t)src[2] * EMBED) + lane));
        float4 v3 = h4_to_f4(*((const uint2*)(g_Vh + (size_t)src[3] * EMBED) + lane));
        // bias per (edge, head): 8 consecutive floats, broadcast within quads
        float b0 = bias[eid[0] * NHEADS + hl];
        float b1 = bias[eid[1] * NHEADS + hl];
        float b2 = bias[eid[2] * NHEADS + hl];
        float b3 = bias[eid[3] * NHEADS + hl];

        float d0 = q.x*k0.x + q.y*k0.y + q.z*k0.z + q.w*k0.w;
        float d1 = q.x*k1.x + q.y*k1.y + q.z*k1.z + q.w*k1.w;
        float d2 = q.x*k2.x + q.y*k2.y + q.z*k2.z + q.w*k2.w;
        float d3 = q.x*k3.x + q.y*k3.y + q.z*k3.z + q.w*k3.w;
        // reduce within quad (xor 1,2) -> every lane holds its head's dot
        d0 += __shfl_xor_sync(0xffffffffu, d0, 1);
        d0 += __shfl_xor_sync(0xffffffffu, d0, 2);
        d1 += __shfl_xor_sync(0xffffffffu, d1, 1);
        d1 += __shfl_xor_sync(0xffffffffu, d1, 2);
        d2 += __shfl_xor_sync(0xffffffffu, d2, 1);
        d2 += __shfl_xor_sync(0xffffffffu, d2, 2);
        d3 += __shfl_xor_sync(0xffffffffu, d3, 1);
        d3 += __shfl_xor_sync(0xffffffffu, d3, 2);

        float l0 = 0.25f * d0 + b0;   // scale = 1/sqrt(16)
        float l1 = 0.25f * d1 + b1;
        float l2 = 0.25f * d2 + b2;
        float l3 = 0.25f * d3 + b3;

        // lane quad-position 0 writes logits for its head (8 lanes -> 8 heads)
        bool w0 = (lane & 3) == 0;
        if (w0)          out_logits[eid[0] * NHEADS + hl] = l0;
        if (w0 && m > 1) out_logits[eid[1] * NHEADS + hl] = l1;
        if (w0 && m > 2) out_logits[eid[2] * NHEADS + hl] = l2;
        if (w0 && m > 3) out_logits[eid[3] * NHEADS + hl] = l3;

        float e0 = __expf(l0);
        float e1 = (m > 1) ? __expf(l1) : 0.0f;
        float e2 = (m > 2) ? __expf(l2) : 0.0f;
        float e3 = (m > 3) ? __expf(l3) : 0.0f;
        accz += e0 + e1 + e2 + e3;

        acc.x += e0*v0.x + e1*v1.x + e2*v2.x + e3*v3.x;
        acc.y += e0*v0.y + e1*v1.y + e2*v2.y + e3*v3.y;
        acc.z += e0*v0.z + e1*v1.z + e2*v2.z + e3*v3.z;
        acc.w += e0*v0.w + e1*v1.w + e2*v2.w + e3*v3.w;
    }

    float inv = (accz > 0.0f) ? (1.0f / accz) : 0.0f;
    acc.x *= inv; acc.y *= inv; acc.z *= inv; acc.w *= inv;
    *(float4*)(g_agg + n * EMBED + lane * 4) = acc;
}

// ---------------- launch --------------------------------------------------
extern "C" void kernel_launch(void* const* d_in, const int* in_sizes, int n_in,
                              void* d_out, int out_size) {
    const float* x    = (const float*)d_in[0];
    const int*   ei   = (const int*)d_in[1];
    const float* bias = (const float*)d_in[2];
    const float* Wq   = (const float*)d_in[3];
    const float* bq   = (const float*)d_in[4];
    const float* Wk   = (const float*)d_in[5];
    const float* bk   = (const float*)d_in[6];
    const float* Wv   = (const float*)d_in[7];
    const float* bv   = (const float*)d_in[8];
    const float* Wo   = (const float*)d_in[9];
    const float* bo   = (const float*)d_in[10];

    float* out        = (float*)d_out;                       // [N_NODES, 128]
    float* out_logits = (float*)d_out + N_NODES * EMBED;     // [E, H, 1]

    init_kernel<<<(N_NODES + 255) / 256, 256>>>();
    hist_kernel<<<(N_EDGES + 255) / 256, 256>>>(ei);
    scan_kernel<<<1, 1024>>>();
    scatter_kernel<<<(N_EDGES + 255) / 256, 256>>>(ei);

    float* gA; cudaGetSymbolAddress((void**)&gA, g_agg);

    int gblk = (N_NODES + GM_BLK - 1) / GM_BLK;
    dim3 qkvgrid(gblk, 3);
    qkv3_kernel<<<qkvgrid, 256>>>(x, Wq, bq, Wk, bk, Wv, bv);

    int nwarp_blocks = (N_NODES * 32 + 255) / 256;
    gather_kernel<<<nwarp_blocks, 256>>>(bias, out_logits);

    gemm_tf32_kernel<<<gblk, 256>>>(gA, Wo, bo, out, N_NODES);
}

// round 13
// speedup vs baseline: 1.1987x; 1.0329x over previous
#include <cuda_runtime.h>
#include <cuda_fp16.h>
#include <math.h>
#include <stdint.h>

#define N_NODES 25000
#define N_EDGES 400000
#define EMBED   128
#define NHEADS  8
#define DKH     16

// ---------------- scratch (static device globals; no allocation) -----------
__device__ __align__(16) __half g_Qh[N_NODES * EMBED];   // fp16 Q (gather-only)
__device__ __align__(16) __half g_Kh[N_NODES * EMBED];   // fp16 K (gather-only)
__device__ __align__(16) __half g_Vh[N_NODES * EMBED];   // fp16 V (gather-only)
__device__ __align__(16) float g_agg[N_NODES * EMBED];   // normalized sum(e*v)/z
__device__ int   g_cnt[N_NODES];                         // edges per dst
__device__ int   g_start[N_NODES];                       // exclusive prefix
__device__ int   g_cur[N_NODES];                         // scatter cursor
__device__ __align__(8) int2 g_sedge[N_EDGES];           // (eid, src) sorted by dst

// ---------------- K0: init (counters only) --------------------------------
__global__ void init_kernel() {
    int i = blockIdx.x * blockDim.x + threadIdx.x;
    if (i < N_NODES) g_cnt[i] = 0;
}

// ---------------- sort by dst: hist -> scan -> scatter ---------------------
__global__ void hist_kernel(const int* __restrict__ ei) {
    int e = blockIdx.x * blockDim.x + threadIdx.x;
    if (e < N_EDGES) atomicAdd(&g_cnt[ei[e]], 1);
}

__global__ void scan_kernel() {   // single block, 1024 threads
    __shared__ int s[1024];
    int t = threadIdx.x;
    const int CH = (N_NODES + 1023) / 1024;   // 25
    int b0 = t * CH;
    int sum = 0;
    for (int i = 0; i < CH; ++i) {
        int idx = b0 + i;
        if (idx < N_NODES) sum += g_cnt[idx];
    }
    s[t] = sum;
    __syncthreads();
    for (int off = 1; off < 1024; off <<= 1) {
        int v = (t >= off) ? s[t - off] : 0;
        __syncthreads();
        s[t] += v;
        __syncthreads();
    }
    int excl = (t == 0) ? 0 : s[t - 1];
    for (int i = 0; i < CH; ++i) {
        int idx = b0 + i;
        if (idx < N_NODES) {
            g_start[idx] = excl;
            g_cur[idx]   = excl;
            excl += g_cnt[idx];
        }
    }
}

__global__ void scatter_kernel(const int* __restrict__ ei) {
    int e = blockIdx.x * blockDim.x + threadIdx.x;
    if (e < N_EDGES) {
        int dst = ei[e];
        int src = ei[N_EDGES + e];
        int pos = atomicAdd(&g_cur[dst], 1);
        g_sedge[pos] = make_int2(e, src);
    }
}

// ================= tf32 tensor-core GEMM: Out = X @ W^T + b ================
#define GM_BLK 128
#define GKC    32

__device__ __forceinline__ float to_tf32(float x) {
    float r;
    asm("cvt.rna.tf32.f32 %0, %1;" : "=f"(r) : "f"(x));
    return r;
}

__device__ __forceinline__ void mma_tf32(float c[4], const unsigned a[4], const unsigned b[2]) {
    asm volatile(
        "mma.sync.aligned.m16n8k8.row.col.f32.tf32.tf32.f32 "
        "{%0,%1,%2,%3}, {%4,%5,%6,%7}, {%8,%9}, {%0,%1,%2,%3};\n"
        : "+f"(c[0]), "+f"(c[1]), "+f"(c[2]), "+f"(c[3])
        : "r"(a[0]), "r"(a[1]), "r"(a[2]), "r"(a[3]), "r"(b[0]), "r"(b[1]));
}

// out_half: if nonzero, Out is a __half* buffer (fp16 store for gather inputs)
__device__ __forceinline__
void gemm_body(const float* __restrict__ X, const float* __restrict__ W,
               const float* __restrict__ bias, void* __restrict__ Out,
               int nrows, float* xs, float* ws, int n0, int out_half) {
    int tid  = threadIdx.x;
    int lane = tid & 31;
    int w    = tid >> 5;

    int mq = w & 3;    // rows 32*mq .. +31
    int nh = w >> 2;   // cols 64*nh .. +63

    float c[2][8][4];
#pragma unroll
    for (int mi = 0; mi < 2; ++mi)
#pragma unroll
        for (int ni = 0; ni < 8; ++ni)
#pragma unroll
            for (int q = 0; q < 4; ++q) c[mi][ni][q] = 0.0f;

    for (int kc = 0; kc < EMBED; kc += GKC) {
#pragma unroll
        for (int r = 0; r < 4; ++r) {
            int idx = r * 256 + tid;
            int n  = idx >> 3;
            int k4 = idx & 7;
            float4 v = make_float4(0.f, 0.f, 0.f, 0.f);
            if (n0 + n < nrows)
                v = *(const float4*)(X + (size_t)(n0 + n) * EMBED + kc + 4 * k4);
            v.x = to_tf32(v.x); v.y = to_tf32(v.y);
            v.z = to_tf32(v.z); v.w = to_tf32(v.w);
            int ks = (4 * k4) ^ ((n & 7) << 2);
            *(float4*)(xs + n * GKC + ks) = v;
        }
#pragma unroll
        for (int r = 0; r < 4; ++r) {
            int idx = r * 256 + tid;
            int j  = idx >> 3;
            int k4 = idx & 7;
            float4 v = *(const float4*)(W + (size_t)j * EMBED + kc + 4 * k4);
            v.x = to_tf32(v.x); v.y = to_tf32(v.y);
            v.z = to_tf32(v.z); v.w = to_tf32(v.w);
            int ks = (4 * k4) ^ ((j & 7) << 2);
            *(float4*)(ws + j * GKC + ks) = v;
        }
        __syncthreads();

#pragma unroll
        for (int k0 = 0; k0 < GKC; k0 += 8) {
            unsigned a[2][4];
#pragma unroll
            for (int mi = 0; mi < 2; ++mi) {
                int rrow = mq * 32 + mi * 16 + (lane >> 2);
                int sw = (rrow & 7) << 2;
                int kA = k0 + (lane & 3);
                a[mi][0] = __float_as_uint(xs[rrow * GKC + (kA ^ sw)]);
                a[mi][1] = __float_as_uint(xs[(rrow + 8) * GKC + (kA ^ sw)]);
                a[mi][2] = __float_as_uint(xs[rrow * GKC + ((kA + 4) ^ sw)]);
                a[mi][3] = __float_as_uint(xs[(rrow + 8) * GKC + ((kA + 4) ^ sw)]);
            }
            unsigned b[8][2];
#pragma unroll
            for (int ni = 0; ni < 8; ++ni) {
                int j = nh * 64 + ni * 8 + (lane >> 2);
                int sw = (j & 7) << 2;
                int kB = k0 + (lane & 3);
                b[ni][0] = __float_as_uint(ws[j * GKC + (kB ^ sw)]);
                b[ni][1] = __float_as_uint(ws[j * GKC + ((kB + 4) ^ sw)]);
            }
#pragma unroll
            for (int mi = 0; mi < 2; ++mi)
#pragma unroll
                for (int ni = 0; ni < 8; ++ni)
                    mma_tf32(c[mi][ni], a[mi], b[ni]);
        }
        __syncthreads();
    }

#pragma unroll
    for (int mi = 0; mi < 2; ++mi) {
        int r = n0 + mq * 32 + mi * 16 + (lane >> 2);
#pragma unroll
        for (int ni = 0; ni < 8; ++ni) {
            int col = nh * 64 + ni * 8 + 2 * (lane & 3);
            float b0 = bias[col], b1 = bias[col + 1];
            if (out_half) {
                __half* Oh = (__half*)Out;
                if (r < nrows)
                    *(__half2*)(Oh + (size_t)r * EMBED + col) =
                        __floats2half2_rn(c[mi][ni][0] + b0, c[mi][ni][1] + b1);
                if (r + 8 < nrows)
                    *(__half2*)(Oh + (size_t)(r + 8) * EMBED + col) =
                        __floats2half2_rn(c[mi][ni][2] + b0, c[mi][ni][3] + b1);
            } else {
                float* Of = (float*)Out;
                if (r < nrows)
                    *(float2*)(Of + (size_t)r * EMBED + col) =
                        make_float2(c[mi][ni][0] + b0, c[mi][ni][1] + b1);
                if (r + 8 < nrows)
                    *(float2*)(Of + (size_t)(r + 8) * EMBED + col) =
                        make_float2(c[mi][ni][2] + b0, c[mi][ni][3] + b1);
            }
        }
    }
}

// fused Q/K/V (fp16 out): blockIdx.y selects projection
__global__ __launch_bounds__(256)
void qkv3_kernel(const float* __restrict__ X,
                 const float* __restrict__ Wq, const float* __restrict__ bq,
                 const float* __restrict__ Wk, const float* __restrict__ bk,
                 const float* __restrict__ Wv, const float* __restrict__ bv) {
    __shared__ float xs[GM_BLK * GKC];
    __shared__ float ws[EMBED * GKC];
    const float* W; const float* b; __half* O;
    if (blockIdx.y == 0)      { W = Wq; b = bq; O = g_Qh; }
    else if (blockIdx.y == 1) { W = Wk; b = bk; O = g_Kh; }
    else                      { W = Wv; b = bv; O = g_Vh; }
    gemm_body(X, W, b, O, N_NODES, xs, ws, blockIdx.x * GM_BLK, 1);
}

__global__ __launch_bounds__(256)
void gemm_tf32_kernel(const float* __restrict__ X,
                      const float* __restrict__ W,
                      const float* __restrict__ bias,
                      float* __restrict__ Out,
                      int nrows) {
    __shared__ float xs[GM_BLK * GKC];
    __shared__ float ws[EMBED * GKC];
    gemm_body(X, W, bias, Out, nrows, xs, ws, blockIdx.x * GM_BLK, 0);
}

// ---------------- gather: shfl-free (edge, head) lane mapping --------------
// One warp per dst node, 4 edges per iteration. lane = el*8 + hl with
// el = lane>>3 (edge slot), hl = lane&7 (head). In fp16 a head slice is
// 16 halves = 32B = one uint4, so lane (el, hl) loads the ENTIRE K slice of
// its (edge, head) with one LDG.128 -- the 8 lanes of an edge group cover
// 256B contiguous (same coalescing as before), but the 16-term dot is now
// fully lane-local: ZERO shuffles in the loop, 1 exp per lane (was 4).
// Indices are fetched by direct broadcast-load (no shfl) and software-
// pipelined one iteration ahead. Cross-edge-group reduction happens once in
// the epilogue (xor 8,16). Softmax shift-invariant (logits O(8), no max
// subtraction); fp32 accumulation; stores NORMALIZED fp32 agg.
__global__ __launch_bounds__(256)
void gather_kernel(const float* __restrict__ bias,
                   float* __restrict__ out_logits) {
    int warp = (blockIdx.x * blockDim.x + threadIdx.x) >> 5;
    if (warp >= N_NODES) return;
    int lane = threadIdx.x & 31;
    int el   = lane >> 3;          // edge slot within iteration group
    int hl   = lane & 7;           // head owned by this lane
    int n = warp;

    // Q slice for head hl -> 16 floats in registers
    float qf[16];
    {
        uint4 qr = *(const uint4*)(g_Qh + (size_t)n * EMBED + hl * DKH);
        const unsigned* qu = (const unsigned*)&qr;
#pragma unroll
        for (int j = 0; j < 4; ++j) {
            float2 fa = __half22float2(*reinterpret_cast<const __half2*>(&qu[j]));
            qf[4 * j + 0] = fa.x; qf[4 * j + 1] = fa.y;
            // second half2 packed in the next 16 bits? No: each unsigned holds
            // one half2 (2 halves). uint4 = 4 unsigned = 8 halves = half slice.
        }
    }
    // uint4 covers only 8 halves; need two uint4 for 16 halves (32B = uint4 x2? )
    // 16 halves = 32 bytes = 2 x uint4. Load second part:
    {
        uint4 qr2 = *(const uint4*)(g_Qh + (size_t)n * EMBED + hl * DKH + 8);
        const unsigned* qu = (const unsigned*)&qr2;
#pragma unroll
        for (int j = 0; j < 4; ++j) {
            float2 fa = __half22float2(*reinterpret_cast<const __half2*>(&qu[j]));
            qf[8 + 2 * j + 0] = fa.x; qf[8 + 2 * j + 1] = fa.y;
        }
    }
    // fix first loop indexing (8 halves -> qf[0..7])
    {
        uint4 qr = *(const uint4*)(g_Qh + (size_t)n * EMBED + hl * DKH);
        const unsigned* qu = (const unsigned*)&qr;
#pragma unroll
        for (int j = 0; j < 4; ++j) {
            float2 fa = __half22float2(*reinterpret_cast<const __half2*>(&qu[j]));
            qf[2 * j + 0] = fa.x; qf[2 * j + 1] = fa.y;
        }
    }

    float acc[16];
#pragma unroll
    for (int j = 0; j < 16; ++j) acc[j] = 0.0f;
    float accz = 0.0f;

    int cnt  = g_cnt[n];
    int base = g_start[n];

    // pipelined index fetch: each lane loads ITS edge's (eid, src) directly
    int2 se = g_sedge[base + min(el, cnt - 1)];

    for (int i = 0; i < cnt; i += 4) {
        int2 cur = se;
        int nxt = i + 4 + el;
        if (nxt < cnt) se = g_sedge[base + nxt];

        bool valid = (i + el) < cnt;
        size_t rowoff = (size_t)cur.y * EMBED + hl * DKH;

        uint4 kr0 = *(const uint4*)(g_Kh + rowoff);
        uint4 kr1 = *(const uint4*)(g_Kh + rowoff + 8);
        uint4 vr0 = *(const uint4*)(g_Vh + rowoff);
        uint4 vr1 = *(const uint4*)(g_Vh + rowoff + 8);
        float bv = bias[cur.x * NHEADS + hl];

        const unsigned* ku0 = (const unsigned*)&kr0;
        const unsigned* ku1 = (const unsigned*)&kr1;
        float dot = 0.0f;
#pragma unroll
        for (int j = 0; j < 4; ++j) {
            float2 fa = __half22float2(*reinterpret_cast<const __half2*>(&ku0[j]));
            dot += qf[2 * j] * fa.x + qf[2 * j + 1] * fa.y;
        }
#pragma unroll
        for (int j = 0; j < 4; ++j) {
            float2 fa = __half22float2(*reinterpret_cast<const __half2*>(&ku1[j]));
            dot += qf[8 + 2 * j] * fa.x + qf[8 + 2 * j + 1] * fa.y;
        }

        float logit = 0.25f * dot + bv;     // scale = 1/sqrt(16)
        if (valid) out_logits[cur.x * NHEADS + hl] = logit;

        float ev = valid ? __expf(logit) : 0.0f;
        accz += ev;

        const unsigned* vu0 = (const unsigned*)&vr0;
        const unsigned* vu1 = (const unsigned*)&vr1;
#pragma unroll
        for (int j = 0; j < 4; ++j) {
            float2 fa = __half22float2(*reinterpret_cast<const __half2*>(&vu0[j]));
            acc[2 * j]     += ev * fa.x;
            acc[2 * j + 1] += ev * fa.y;
        }
#pragma unroll
        for (int j = 0; j < 4; ++j) {
            float2 fa = __half22float2(*reinterpret_cast<const __half2*>(&vu1[j]));
            acc[8 + 2 * j]     += ev * fa.x;
            acc[8 + 2 * j + 1] += ev * fa.y;
        }
    }

    // one-time cross-edge-group reduction (lanes differing in bits 3,4)
    accz += __shfl_xor_sync(0xffffffffu, accz, 8);
    accz += __shfl_xor_sync(0xffffffffu, accz, 16);
#pragma unroll
    for (int j = 0; j < 16; ++j) {
        acc[j] += __shfl_xor_sync(0xffffffffu, acc[j], 8);
        acc[j] += __shfl_xor_sync(0xffffffffu, acc[j], 16);
    }

    float inv = (accz > 0.0f) ? (1.0f / accz) : 0.0f;
    // lane writes its el-quarter of head hl's slice
    float4 wv = make_float4(acc[el * 4 + 0] * inv, acc[el * 4 + 1] * inv,
                            acc[el * 4 + 2] * inv, acc[el * 4 + 3] * inv);
    *(float4*)(g_agg + (size_t)n * EMBED + hl * DKH + el * 4) = wv;
}

// ---------------- launch --------------------------------------------------
extern "C" void kernel_launch(void* const* d_in, const int* in_sizes, int n_in,
                              void* d_out, int out_size) {
    const float* x    = (const float*)d_in[0];
    const int*   ei   = (const int*)d_in[1];
    const float* bias = (const float*)d_in[2];
    const float* Wq   = (const float*)d_in[3];
    const float* bq   = (const float*)d_in[4];
    const float* Wk   = (const float*)d_in[5];
    const float* bk   = (const float*)d_in[6];
    const float* Wv   = (const float*)d_in[7];
    const float* bv   = (const float*)d_in[8];
    const float* Wo   = (const float*)d_in[9];
    const float* bo   = (const float*)d_in[10];

    float* out        = (float*)d_out;                       // [N_NODES, 128]
    float* out_logits = (float*)d_out + N_NODES * EMBED;     // [E, H, 1]

    init_kernel<<<(N_NODES + 255) / 256, 256>>>();
    hist_kernel<<<(N_EDGES + 255) / 256, 256>>>(ei);
    scan_kernel<<<1, 1024>>>();
    scatter_kernel<<<(N_EDGES + 255) / 256, 256>>>(ei);

    float* gA; cudaGetSymbolAddress((void**)&gA, g_agg);

    int gblk = (N_NODES + GM_BLK - 1) / GM_BLK;
    dim3 qkvgrid(gblk, 3);
    qkv3_kernel<<<qkvgrid, 256>>>(x, Wq, bq, Wk, bk, Wv, bv);

    int nwarp_blocks = (N_NODES * 32 + 255) / 256;
    gather_kernel<<<nwarp_blocks, 256>>>(bias, out_logits);

    gemm_tf32_kernel<<<gblk, 256>>>(gA, Wo, bo, out, N_NODES);
}

// round 15
// speedup vs baseline: 1.2257x; 1.0225x over previous
#include <cuda_runtime.h>
#include <cuda_fp16.h>
#include <math.h>
#include <stdint.h>

#define N_NODES 25000
#define N_EDGES 400000
#define EMBED   128
#define NHEADS  8
#define DKH     16

// ---------------- scratch (static device globals; no allocation) -----------
__device__ __align__(16) __half g_Qh[N_NODES * EMBED];   // fp16 Q (gather-only)
__device__ __align__(16) __half g_Kh[N_NODES * EMBED];   // fp16 K (gather-only)
__device__ __align__(16) __half g_Vh[N_NODES * EMBED];   // fp16 V (gather-only)
__device__ __align__(16) float g_agg[N_NODES * EMBED];   // normalized sum(e*v)/z
__device__ int   g_cnt[N_NODES];                         // edges per dst
__device__ int   g_start[N_NODES];                       // exclusive prefix
__device__ int   g_cur[N_NODES];                         // scatter cursor
__device__ __align__(8) int2 g_sedge[N_EDGES];           // (eid, src) sorted by dst

// ---------------- K0: init (counters only) --------------------------------
__global__ void init_kernel() {
    int i = blockIdx.x * blockDim.x + threadIdx.x;
    if (i < N_NODES) g_cnt[i] = 0;
}

// ---------------- sort by dst: hist -> scan -> scatter ---------------------
__global__ void hist_kernel(const int* __restrict__ ei) {
    int e = blockIdx.x * blockDim.x + threadIdx.x;
    if (e < N_EDGES) atomicAdd(&g_cnt[ei[e]], 1);
}

__global__ void scan_kernel() {   // single block, 1024 threads
    __shared__ int s[1024];
    int t = threadIdx.x;
    const int CH = (N_NODES + 1023) / 1024;   // 25
    int b0 = t * CH;
    int sum = 0;
    for (int i = 0; i < CH; ++i) {
        int idx = b0 + i;
        if (idx < N_NODES) sum += g_cnt[idx];
    }
    s[t] = sum;
    __syncthreads();
    for (int off = 1; off < 1024; off <<= 1) {
        int v = (t >= off) ? s[t - off] : 0;
        __syncthreads();
        s[t] += v;
        __syncthreads();
    }
    int excl = (t == 0) ? 0 : s[t - 1];
    for (int i = 0; i < CH; ++i) {
        int idx = b0 + i;
        if (idx < N_NODES) {
            g_start[idx] = excl;
            g_cur[idx]   = excl;
            excl += g_cnt[idx];
        }
    }
}

__global__ void scatter_kernel(const int* __restrict__ ei) {
    int e = blockIdx.x * blockDim.x + threadIdx.x;
    if (e < N_EDGES) {
        int dst = ei[e];
        int src = ei[N_EDGES + e];
        int pos = atomicAdd(&g_cur[dst], 1);
        g_sedge[pos] = make_int2(e, src);
    }
}

// ================= tf32 tensor-core GEMM: Out = X @ W^T + b ================
#define GM_BLK 128
#define GKC    32

__device__ __forceinline__ float to_tf32(float x) {
    float r;
    asm("cvt.rna.tf32.f32 %0, %1;" : "=f"(r) : "f"(x));
    return r;
}

__device__ __forceinline__ void mma_tf32(float c[4], const unsigned a[4], const unsigned b[2]) {
    asm volatile(
        "mma.sync.aligned.m16n8k8.row.col.f32.tf32.tf32.f32 "
        "{%0,%1,%2,%3}, {%4,%5,%6,%7}, {%8,%9}, {%0,%1,%2,%3};\n"
        : "+f"(c[0]), "+f"(c[1]), "+f"(c[2]), "+f"(c[3])
        : "r"(a[0]), "r"(a[1]), "r"(a[2]), "r"(a[3]), "r"(b[0]), "r"(b[1]));
}

// out_half: if nonzero, Out is a __half* buffer (fp16 store for gather inputs)
__device__ __forceinline__
void gemm_body(const float* __restrict__ X, const float* __restrict__ W,
               const float* __restrict__ bias, void* __restrict__ Out,
               int nrows, float* xs, float* ws, int n0, int out_half) {
    int tid  = threadIdx.x;
    int lane = tid & 31;
    int w    = tid >> 5;

    int mq = w & 3;    // rows 32*mq .. +31
    int nh = w >> 2;   // cols 64*nh .. +63

    float c[2][8][4];
#pragma unroll
    for (int mi = 0; mi < 2; ++mi)
#pragma unroll
        for (int ni = 0; ni < 8; ++ni)
#pragma unroll
            for (int q = 0; q < 4; ++q) c[mi][ni][q] = 0.0f;

    for (int kc = 0; kc < EMBED; kc += GKC) {
#pragma unroll
        for (int r = 0; r < 4; ++r) {
            int idx = r * 256 + tid;
            int n  = idx >> 3;
            int k4 = idx & 7;
            float4 v = make_float4(0.f, 0.f, 0.f, 0.f);
            if (n0 + n < nrows)
                v = *(const float4*)(X + (size_t)(n0 + n) * EMBED + kc + 4 * k4);
            v.x = to_tf32(v.x); v.y = to_tf32(v.y);
            v.z = to_tf32(v.z); v.w = to_tf32(v.w);
            int ks = (4 * k4) ^ ((n & 7) << 2);
            *(float4*)(xs + n * GKC + ks) = v;
        }
#pragma unroll
        for (int r = 0; r < 4; ++r) {
            int idx = r * 256 + tid;
            int j  = idx >> 3;
            int k4 = idx & 7;
            float4 v = *(const float4*)(W + (size_t)j * EMBED + kc + 4 * k4);
            v.x = to_tf32(v.x); v.y = to_tf32(v.y);
            v.z = to_tf32(v.z); v.w = to_tf32(v.w);
            int ks = (4 * k4) ^ ((j & 7) << 2);
            *(float4*)(ws + j * GKC + ks) = v;
        }
        __syncthreads();

#pragma unroll
        for (int k0 = 0; k0 < GKC; k0 += 8) {
            unsigned a[2][4];
#pragma unroll
            for (int mi = 0; mi < 2; ++mi) {
                int rrow = mq * 32 + mi * 16 + (lane >> 2);
                int sw = (rrow & 7) << 2;
                int kA = k0 + (lane & 3);
                a[mi][0] = __float_as_uint(xs[rrow * GKC + (kA ^ sw)]);
                a[mi][1] = __float_as_uint(xs[(rrow + 8) * GKC + (kA ^ sw)]);
                a[mi][2] = __float_as_uint(xs[rrow * GKC + ((kA + 4) ^ sw)]);
                a[mi][3] = __float_as_uint(xs[(rrow + 8) * GKC + ((kA + 4) ^ sw)]);
            }
            unsigned b[8][2];
#pragma unroll
            for (int ni = 0; ni < 8; ++ni) {
                int j = nh * 64 + ni * 8 + (lane >> 2);
                int sw = (j & 7) << 2;
                int kB = k0 + (lane & 3);
                b[ni][0] = __float_as_uint(ws[j * GKC + (kB ^ sw)]);
                b[ni][1] = __float_as_uint(ws[j * GKC + ((kB + 4) ^ sw)]);
            }
#pragma unroll
            for (int mi = 0; mi < 2; ++mi)
#pragma unroll
                for (int ni = 0; ni < 8; ++ni)
                    mma_tf32(c[mi][ni], a[mi], b[ni]);
        }
        __syncthreads();
    }

#pragma unroll
    for (int mi = 0; mi < 2; ++mi) {
        int r = n0 + mq * 32 + mi * 16 + (lane >> 2);
#pragma unroll
        for (int ni = 0; ni < 8; ++ni) {
            int col = nh * 64 + ni * 8 + 2 * (lane & 3);
            float b0 = bias[col], b1 = bias[col + 1];
            if (out_half) {
                __half* Oh = (__half*)Out;
                if (r < nrows)
                    *(__half2*)(Oh + (size_t)r * EMBED + col) =
                        __floats2half2_rn(c[mi][ni][0] + b0, c[mi][ni][1] + b1);
                if (r + 8 < nrows)
                    *(__half2*)(Oh + (size_t)(r + 8) * EMBED + col) =
                        __floats2half2_rn(c[mi][ni][2] + b0, c[mi][ni][3] + b1);
            } else {
                float* Of = (float*)Out;
                if (r < nrows)
                    *(float2*)(Of + (size_t)r * EMBED + col) =
                        make_float2(c[mi][ni][0] + b0, c[mi][ni][1] + b1);
                if (r + 8 < nrows)
                    *(float2*)(Of + (size_t)(r + 8) * EMBED + col) =
                        make_float2(c[mi][ni][2] + b0, c[mi][ni][3] + b1);
            }
        }
    }
}

// fused Q/K/V (fp16 out): blockIdx.y selects projection
__global__ __launch_bounds__(256)
void qkv3_kernel(const float* __restrict__ X,
                 const float* __restrict__ Wq, const float* __restrict__ bq,
                 const float* __restrict__ Wk, const float* __restrict__ bk,
                 const float* __restrict__ Wv, const float* __restrict__ bv) {
    __shared__ float xs[GM_BLK * GKC];
    __shared__ float ws[EMBED * GKC];
    const float* W; const float* b; __half* O;
    if (blockIdx.y == 0)      { W = Wq; b = bq; O = g_Qh; }
    else if (blockIdx.y == 1) { W = Wk; b = bk; O = g_Kh; }
    else                      { W = Wv; b = bv; O = g_Vh; }
    gemm_body(X, W, b, O, N_NODES, xs, ws, blockIdx.x * GM_BLK, 1);
}

__global__ __launch_bounds__(256)
void gemm_tf32_kernel(const float* __restrict__ X,
                      const float* __restrict__ W,
                      const float* __restrict__ bias,
                      float* __restrict__ Out,
                      int nrows) {
    __shared__ float xs[GM_BLK * GKC];
    __shared__ float ws[EMBED * GKC];
    gemm_body(X, W, bias, Out, nrows, xs, ws, blockIdx.x * GM_BLK, 0);
}

// ---------------- gather: shfl-free (edge, head) lane mapping --------------
// One warp per dst node, 4 edges per iteration. lane = el*8 + hl with
// el = lane>>3 (edge slot), hl = lane&7 (head). fp16 head slice = 16 halves
// = 32B = two uint4 loads; the 16-term dot is fully lane-local: ZERO shuffles
// in the loop, 1 exp per lane. Indices fetched per-lane and software-
// pipelined one iteration ahead. Cross-edge-group reduction once in the
// epilogue (xor 8,16). Softmax shift-invariant (logits O(8), no max
// subtraction); fp32 accumulation; stores NORMALIZED fp32 agg.
__global__ __launch_bounds__(256)
void gather_kernel(const float* __restrict__ bias,
                   float* __restrict__ out_logits) {
    int warp = (blockIdx.x * blockDim.x + threadIdx.x) >> 5;
    if (warp >= N_NODES) return;
    int lane = threadIdx.x & 31;
    int el   = lane >> 3;          // edge slot within iteration group
    int hl   = lane & 7;           // head owned by this lane
    int n = warp;

    // Q slice for head hl -> 16 floats in registers (two uint4 = 16 halves)
    float qf[16];
    {
        uint4 qr0 = *(const uint4*)(g_Qh + (size_t)n * EMBED + hl * DKH);
        uint4 qr1 = *(const uint4*)(g_Qh + (size_t)n * EMBED + hl * DKH + 8);
        const unsigned* qu0 = (const unsigned*)&qr0;
        const unsigned* qu1 = (const unsigned*)&qr1;
#pragma unroll
        for (int j = 0; j < 4; ++j) {
            float2 fa = __half22float2(*reinterpret_cast<const __half2*>(&qu0[j]));
            qf[2 * j + 0] = fa.x; qf[2 * j + 1] = fa.y;
            float2 fb = __half22float2(*reinterpret_cast<const __half2*>(&qu1[j]));
            qf[8 + 2 * j + 0] = fb.x; qf[8 + 2 * j + 1] = fb.y;
        }
    }

    float acc[16];
#pragma unroll
    for (int j = 0; j < 16; ++j) acc[j] = 0.0f;
    float accz = 0.0f;

    int cnt  = g_cnt[n];
    int base = g_start[n];

    // pipelined index fetch: each lane loads ITS edge's (eid, src) directly
    int2 se = g_sedge[base + min(el, cnt - 1)];

    for (int i = 0; i < cnt; i += 4) {
        int2 cur = se;
        int nxt = i + 4 + el;
        if (nxt < cnt) se = g_sedge[base + nxt];

        bool valid = (i + el) < cnt;
        size_t rowoff = (size_t)cur.y * EMBED + hl * DKH;

        uint4 kr0 = *(const uint4*)(g_Kh + rowoff);
        uint4 kr1 = *(const uint4*)(g_Kh + rowoff + 8);
        uint4 vr0 = *(const uint4*)(g_Vh + rowoff);
        uint4 vr1 = *(const uint4*)(g_Vh + rowoff + 8);
        float bv = bias[cur.x * NHEADS + hl];

        const unsigned* ku0 = (const unsigned*)&kr0;
        const unsigned* ku1 = (const unsigned*)&kr1;
        float dot = 0.0f;
#pragma unroll
        for (int j = 0; j < 4; ++j) {
            float2 fa = __half22float2(*reinterpret_cast<const __half2*>(&ku0[j]));
            dot += qf[2 * j] * fa.x + qf[2 * j + 1] * fa.y;
        }
#pragma unroll
        for (int j = 0; j < 4; ++j) {
            float2 fa = __half22float2(*reinterpret_cast<const __half2*>(&ku1[j]));
            dot += qf[8 + 2 * j] * fa.x + qf[8 + 2 * j + 1] * fa.y;
        }

        float logit = 0.25f * dot + bv;     // scale = 1/sqrt(16)
        if (valid) out_logits[cur.x * NHEADS + hl] = logit;

        float ev = valid ? __expf(logit) : 0.0f;
        accz += ev;

        const unsigned* vu0 = (const unsigned*)&vr0;
        const unsigned* vu1 = (const unsigned*)&vr1;
#pragma unroll
        for (int j = 0; j < 4; ++j) {
            float2 fa = __half22float2(*reinterpret_cast<const __half2*>(&vu0[j]));
            acc[2 * j]     += ev * fa.x;
            acc[2 * j + 1] += ev * fa.y;
        }
#pragma unroll
        for (int j = 0; j < 4; ++j) {
            float2 fa = __half22float2(*reinterpret_cast<const __half2*>(&vu1[j]));
            acc[8 + 2 * j]     += ev * fa.x;
            acc[8 + 2 * j + 1] += ev * fa.y;
        }
    }

    // one-time cross-edge-group reduction (lanes differing in bits 3,4)
    accz += __shfl_xor_sync(0xffffffffu, accz, 8);
    accz += __shfl_xor_sync(0xffffffffu, accz, 16);
#pragma unroll
    for (int j = 0; j < 16; ++j) {
        acc[j] += __shfl_xor_sync(0xffffffffu, acc[j], 8);
        acc[j] += __shfl_xor_sync(0xffffffffu, acc[j], 16);
    }

    float inv = (accz > 0.0f) ? (1.0f / accz) : 0.0f;
    // lane writes its el-quarter of head hl's slice
    float4 wv = make_float4(acc[el * 4 + 0] * inv, acc[el * 4 + 1] * inv,
                            acc[el * 4 + 2] * inv, acc[el * 4 + 3] * inv);
    *(float4*)(g_agg + (size_t)n * EMBED + hl * DKH + el * 4) = wv;
}

// ---------------- launch --------------------------------------------------
// Prep chain (init/hist/scan/scatter) is independent of qkv3; run it on a
// side stream forked/joined with events so it overlaps the QKV GEMM inside
// the captured graph. Streams/events are created lazily on the FIRST call
// (the uncaptured correctness run) and reused on every captured call.
extern "C" void kernel_launch(void* const* d_in, const int* in_sizes, int n_in,
                              void* d_out, int out_size) {
    const float* x    = (const float*)d_in[0];
    const int*   ei   = (const int*)d_in[1];
    const float* bias = (const float*)d_in[2];
    const float* Wq   = (const float*)d_in[3];
    const float* bq   = (const float*)d_in[4];
    const float* Wk   = (const float*)d_in[5];
    const float* bk   = (const float*)d_in[6];
    const float* Wv   = (const float*)d_in[7];
    const float* bv   = (const float*)d_in[8];
    const float* Wo   = (const float*)d_in[9];
    const float* bo   = (const float*)d_in[10];

    float* out        = (float*)d_out;                       // [N_NODES, 128]
    float* out_logits = (float*)d_out + N_NODES * EMBED;     // [E, H, 1]

    static cudaStream_t s2 = nullptr;
    static cudaEvent_t ev_fork = nullptr, ev_join = nullptr;
    if (s2 == nullptr) {
        cudaStreamCreateWithFlags(&s2, cudaStreamNonBlocking);
        cudaEventCreateWithFlags(&ev_fork, cudaEventDisableTiming);
        cudaEventCreateWithFlags(&ev_join, cudaEventDisableTiming);
    }

    // fork: s2 ordered after anything already on the main (default) stream
    cudaEventRecord(ev_fork, 0);
    cudaStreamWaitEvent(s2, ev_fork, 0);

    // prep chain on side stream
    init_kernel<<<(N_NODES + 255) / 256, 256, 0, s2>>>();
    hist_kernel<<<(N_EDGES + 255) / 256, 256, 0, s2>>>(ei);
    scan_kernel<<<1, 1024, 0, s2>>>();
    scatter_kernel<<<(N_EDGES + 255) / 256, 256, 0, s2>>>(ei);
    cudaEventRecord(ev_join, s2);

    // QKV GEMM on main stream, concurrent with prep
    int gblk = (N_NODES + GM_BLK - 1) / GM_BLK;
    dim3 qkvgrid(gblk, 3);
    qkv3_kernel<<<qkvgrid, 256>>>(x, Wq, bq, Wk, bk, Wv, bv);

    // join: gather needs both qkv3 (main) and prep (s2)
    cudaStreamWaitEvent(0, ev_join, 0);

    int nwarp_blocks = (N_NODES * 32 + 255) / 256;
    gather_kernel<<<nwarp_blocks, 256>>>(bias, out_logits);

    float* gA; cudaGetSymbolAddress((void**)&gA, g_agg);
    gemm_tf32_kernel<<<gblk, 256>>>(gA, Wo, bo, out, N_NODES);
}